// round 11
// baseline (speedup 1.0000x reference)
#include <cuda_runtime.h>
#include <cuda_bf16.h>
#include <cuda_fp16.h>
#include <cstdint>

#define BB 8
#define TT 2048
#define EE 1024
#define HS 64
#define NTOT 192   // q(64) | k(64) | v(64)
#define ROWS (BB * TT)
#define PSTRIDE (BB * TT * HS)

// Preconverted operands (written by qkv epilogue)
__device__ __nv_bfloat16 g_qh[ROWS * HS];   // Q hi, pre-scaled 0.125, [B*T][64]
__device__ __nv_bfloat16 g_ql[ROWS * HS];
__device__ __nv_bfloat16 g_kh[ROWS * HS];   // K hi [B*T][64]
__device__ __nv_bfloat16 g_kl[ROWS * HS];
__device__ __half        g_vth[BB * HS * TT];  // V transposed [B][64h][2048t], fp16
// Weights fp16 hi/lo of (32*W)
__device__ __half g_Wh[NTOT * EE];
__device__ __half g_Wl[NTOT * EE];
// Attention partials (2 key-split parts)
__device__ float g_pO[2 * PSTRIDE];
__device__ float g_pm[2 * ROWS];
__device__ float g_pl[2 * ROWS];
// Per-tile arrival flags (parity-based: never reset; second arrival merges)
__device__ int g_flag[BB * 32];

// ---------------------------------------------------------------------------
// Helpers
// ---------------------------------------------------------------------------
__device__ __forceinline__ uint32_t smem_u32(const void* p) {
    uint32_t a;
    asm("{ .reg .u64 t; cvta.to.shared.u64 t, %1; cvt.u32.u64 %0, t; }"
        : "=r"(a) : "l"(p));
    return a;
}

__device__ __forceinline__ void cp16(uint32_t dst, const void* src) {
    asm volatile("cp.async.cg.shared.global [%0], [%1], 16;"
                 :: "r"(dst), "l"(src));
}

// bf16 mma, fp32 accum
__device__ __forceinline__ void mma16816(float* c, const uint32_t* a,
                                         const uint32_t* b) {
    asm volatile(
        "mma.sync.aligned.m16n8k16.row.col.f32.bf16.bf16.f32 "
        "{%0,%1,%2,%3}, {%4,%5,%6,%7}, {%8,%9}, {%0,%1,%2,%3};"
        : "+f"(c[0]), "+f"(c[1]), "+f"(c[2]), "+f"(c[3])
        : "r"(a[0]), "r"(a[1]), "r"(a[2]), "r"(a[3]), "r"(b[0]), "r"(b[1]));
}

// fp16 mma, fp32 accum
__device__ __forceinline__ void mma16816h(float* c, const uint32_t* a,
                                          const uint32_t* b) {
    asm volatile(
        "mma.sync.aligned.m16n8k16.row.col.f32.f16.f16.f32 "
        "{%0,%1,%2,%3}, {%4,%5,%6,%7}, {%8,%9}, {%0,%1,%2,%3};"
        : "+f"(c[0]), "+f"(c[1]), "+f"(c[2]), "+f"(c[3])
        : "r"(a[0]), "r"(a[1]), "r"(a[2]), "r"(a[3]), "r"(b[0]), "r"(b[1]));
}

// ldmatrix x4 (non-trans, b16)
__device__ __forceinline__ void ldmx4(uint32_t* r, uint32_t addr) {
    asm volatile(
        "ldmatrix.sync.aligned.m8n8.x4.shared.b16 {%0,%1,%2,%3}, [%4];"
        : "=r"(r[0]), "=r"(r[1]), "=r"(r[2]), "=r"(r[3]) : "r"(addr));
}

// ---------------------------------------------------------------------------
// Kernel 0: convert concat(Wq,Wk,Wv)*32 fp32 -> fp16 hi/lo, [192][1024]
// ILP x4: each thread handles 4 strided float4s (MLP=4).
// ---------------------------------------------------------------------------
__global__ __launch_bounds__(256) void w_convert_kernel(
    const float* __restrict__ Wq, const float* __restrict__ Wk,
    const float* __restrict__ Wv)
{
    int t = blockIdx.x * 256 + threadIdx.x;      // 12288 threads
    #pragma unroll
    for (int i = 0; i < 4; i++) {
        int idx = t + i * 12288;                 // 49152 float4s total
        int e4 = idx * 4;
        int n = e4 >> 10;
        int c = e4 & 1023;
        const float* src = (n < 64) ? &Wq[n * 1024 + c]
                         : (n < 128) ? &Wk[(n - 64) * 1024 + c]
                         : &Wv[(n - 128) * 1024 + c];
        float4 v = *(const float4*)src;
        float vs[4] = {v.x * 32.0f, v.y * 32.0f, v.z * 32.0f, v.w * 32.0f};
        __half h[4], l[4];
        #pragma unroll
        for (int e = 0; e < 4; e++) {
            h[e] = __float2half_rn(vs[e]);
            l[e] = __float2half_rn(vs[e] - __half2float(h[e]));
        }
        *(uint2*)&g_Wh[e4] = *(uint2*)h;
        *(uint2*)&g_Wl[e4] = *(uint2*)l;
    }
}

// ---------------------------------------------------------------------------
// Kernel 1: QKV projection, fp16 2-term mma (exact R7).
// ---------------------------------------------------------------------------
#define ASTRIDE 80
#define BOFF  10240
#define STAGE 34816
#define SMEM_QKV (2 * STAGE)

__global__ void __launch_bounds__(256) qkv_mma_kernel(
    const float* __restrict__ X,
    const float* __restrict__ bq, const float* __restrict__ bk,
    const float* __restrict__ bv)
{
    extern __shared__ __align__(128) char sm[];
    const uint32_t smb = smem_u32(sm);
    const int tid = threadIdx.x;
    const int lid = tid & 31;
    const int wid = tid >> 5;
    const int wm  = wid >> 2;
    const int wn  = wid & 3;
    const int lg  = lid >> 2;
    const int lt  = lid & 3;
    const int m0  = blockIdx.x * 128;
    const int arow = tid >> 1;
    const int akh  = tid & 1;

    float acc[4][6][4];
    #pragma unroll
    for (int t = 0; t < 4; t++)
        #pragma unroll
        for (int u = 0; u < 6; u++)
            #pragma unroll
            for (int r = 0; r < 4; r++) acc[t][u][r] = 0.0f;

    float4 xr[4];

    {
        const float* xp = &X[(size_t)(m0 + arow) * EE + akh * 16];
        #pragma unroll
        for (int p = 0; p < 4; p++) xr[p] = *(const float4*)&xp[p * 4];
        #pragma unroll
        for (int j = 0; j < 6; j++) {
            int idx = j * 256 + tid;
            int n = idx >> 3, u = idx & 7;
            int kg = u & 3, wh = u >> 2;
            const __half* s = (wh ? g_Wl : g_Wh) + n * EE + kg * 8;
            cp16(smb + BOFF + n * 128 + ((u ^ (n & 7)) * 16), s);
        }
        asm volatile("cp.async.commit_group;");
        {
            __half2 hh[8];
            #pragma unroll
            for (int p = 0; p < 4; p++) {
                hh[2 * p]     = __floats2half2_rn(xr[p].x, xr[p].y);
                hh[2 * p + 1] = __floats2half2_rn(xr[p].z, xr[p].w);
            }
            *(uint4*)(sm + arow * ASTRIDE + akh * 32)      = *(uint4*)&hh[0];
            *(uint4*)(sm + arow * ASTRIDE + akh * 32 + 16) = *(uint4*)&hh[4];
        }
        asm volatile("cp.async.wait_group 0;");
        __syncthreads();
    }

    for (int c = 0; c < 32; c++) {
        const int cb = c & 1;
        const int nb = (c + 1) & 1;
        if (c < 31) {
            const int k0 = (c + 1) * 32;
            const float* xp = &X[(size_t)(m0 + arow) * EE + k0 + akh * 16];
            #pragma unroll
            for (int p = 0; p < 4; p++) xr[p] = *(const float4*)&xp[p * 4];
            #pragma unroll
            for (int j = 0; j < 6; j++) {
                int idx = j * 256 + tid;
                int n = idx >> 3, u = idx & 7;
                int kg = u & 3, wh = u >> 2;
                const __half* s = (wh ? g_Wl : g_Wh) + n * EE + k0 + kg * 8;
                cp16(smb + nb * STAGE + BOFF + n * 128 + ((u ^ (n & 7)) * 16), s);
            }
            asm volatile("cp.async.commit_group;");
        }

        const char* ab = sm + cb * STAGE;
        const char* bb = ab + BOFF;
        #pragma unroll
        for (int h = 0; h < 2; h++) {
            uint32_t af[4][4], bfh[6][2], bfl[6][2];
            #pragma unroll
            for (int t = 0; t < 4; t++) {
                int r  = wm * 64 + t * 16 + lg;
                int r8 = r + 8;
                af[t][0] = *(const uint32_t*)(ab + r  * ASTRIDE + (2 * h) * 16 + lt * 4);
                af[t][1] = *(const uint32_t*)(ab + r8 * ASTRIDE + (2 * h) * 16 + lt * 4);
                af[t][2] = *(const uint32_t*)(ab + r  * ASTRIDE + (2 * h + 1) * 16 + lt * 4);
                af[t][3] = *(const uint32_t*)(ab + r8 * ASTRIDE + (2 * h + 1) * 16 + lt * 4);
            }
            #pragma unroll
            for (int u = 0; u < 6; u++) {
                int n = wn * 48 + u * 8 + lg;
                int kg0 = 2 * h, kg1 = 2 * h + 1;
                bfh[u][0] = *(const uint32_t*)(bb + n * 128 + ((kg0 ^ (n & 7)) * 16) + lt * 4);
                bfh[u][1] = *(const uint32_t*)(bb + n * 128 + ((kg1 ^ (n & 7)) * 16) + lt * 4);
                bfl[u][0] = *(const uint32_t*)(bb + n * 128 + (((kg0 | 4) ^ (n & 7)) * 16) + lt * 4);
                bfl[u][1] = *(const uint32_t*)(bb + n * 128 + (((kg1 | 4) ^ (n & 7)) * 16) + lt * 4);
            }
            #pragma unroll
            for (int t = 0; t < 4; t++)
                #pragma unroll
                for (int u = 0; u < 6; u++)
                    mma16816h(acc[t][u], af[t], bfh[u]);
            #pragma unroll
            for (int t = 0; t < 4; t++)
                #pragma unroll
                for (int u = 0; u < 6; u++)
                    mma16816h(acc[t][u], af[t], bfl[u]);
        }

        if (c < 31) {
            __half2 hh[8];
            #pragma unroll
            for (int p = 0; p < 4; p++) {
                hh[2 * p]     = __floats2half2_rn(xr[p].x, xr[p].y);
                hh[2 * p + 1] = __floats2half2_rn(xr[p].z, xr[p].w);
            }
            *(uint4*)(sm + nb * STAGE + arow * ASTRIDE + akh * 32)      = *(uint4*)&hh[0];
            *(uint4*)(sm + nb * STAGE + arow * ASTRIDE + akh * 32 + 16) = *(uint4*)&hh[4];
            asm volatile("cp.async.wait_group 0;");
        }
        __syncthreads();
    }

    // ---- epilogue: acc/32 + bias; Q/K -> bf16 hi/lo; V -> fp16 via smem T
    __half* VtSh = (__half*)sm;                  // [64h][128 rl]

    #pragma unroll
    for (int t = 0; t < 4; t++) {
        int rl = wm * 64 + t * 16 + lg;
        size_t rg = (size_t)(m0 + rl);
        #pragma unroll
        for (int u = 0; u < 6; u++) {
            int n = wn * 48 + u * 8 + lt * 2;
            const float* barr; int col; int kind;
            if (n < 64)       { col = n;       barr = bq; kind = 0; }
            else if (n < 128) { col = n - 64;  barr = bk; kind = 1; }
            else              { col = n - 128; barr = bv; kind = 2; }
            float b0 = __ldg(&barr[col]), b1 = __ldg(&barr[col + 1]);
            float v00 = acc[t][u][0] * 0.03125f + b0;
            float v01 = acc[t][u][1] * 0.03125f + b1;
            float v10 = acc[t][u][2] * 0.03125f + b0;
            float v11 = acc[t][u][3] * 0.03125f + b1;
            if (kind == 0) {
                v00 *= 0.125f; v01 *= 0.125f; v10 *= 0.125f; v11 *= 0.125f;
            }
            if (kind < 2) {
                __nv_bfloat16* dh = kind ? g_kh : g_qh;
                __nv_bfloat16* dl = kind ? g_kl : g_ql;
                __nv_bfloat162 h0p = __floats2bfloat162_rn(v00, v01);
                float2 f0 = __bfloat1622float2(h0p);
                __nv_bfloat162 l0p = __floats2bfloat162_rn(v00 - f0.x, v01 - f0.y);
                __nv_bfloat162 h1p = __floats2bfloat162_rn(v10, v11);
                float2 f1 = __bfloat1622float2(h1p);
                __nv_bfloat162 l1p = __floats2bfloat162_rn(v10 - f1.x, v11 - f1.y);
                *(uint32_t*)&dh[rg * HS + col]       = *(uint32_t*)&h0p;
                *(uint32_t*)&dl[rg * HS + col]       = *(uint32_t*)&l0p;
                *(uint32_t*)&dh[(rg + 8) * HS + col] = *(uint32_t*)&h1p;
                *(uint32_t*)&dl[(rg + 8) * HS + col] = *(uint32_t*)&l1p;
            } else {
                VtSh[col * 128 + rl]           = __float2half_rn(v00);
                VtSh[(col + 1) * 128 + rl]     = __float2half_rn(v01);
                VtSh[col * 128 + rl + 8]       = __float2half_rn(v10);
                VtSh[(col + 1) * 128 + rl + 8] = __float2half_rn(v11);
            }
        }
    }
    __syncthreads();
    {
        int bbb = m0 >> 11, t0 = m0 & 2047;
        #pragma unroll
        for (int q = 0; q < 4; q++) {
            int idx = q * 256 + tid;
            int h = idx >> 4, cc = idx & 15;
            __half* dst = g_vth + ((size_t)(bbb * HS + h)) * TT + t0 + cc * 8;
            *(uint4*)dst = *(const uint4*)(VtSh + h * 128 + cc * 8);
        }
    }
}

// ---------------------------------------------------------------------------
// Kernel 2: causal flash attention (exact R7 core) + fused combine tail.
// Key-split x2 + triangle pairing; 2-stage pipeline; the SECOND CTA of each
// tile pair (parity of g_flag arrival) merges both partials and writes out.
// ---------------------------------------------------------------------------
#define STG 27648

#define LOADSTAGE(st_, kt_) do {                                              \
    uint32_t sb_ = smb + (st_) * STG;                                         \
    size_t kbase_ = ((size_t)b * TT + (size_t)(kt_) * 64) * HS;               \
    size_t vbase_ = (size_t)b * (HS * TT) + (size_t)(kt_) * 64;               \
    _Pragma("unroll")                                                         \
    for (int q_ = 0; q_ < 4; q_++) {                                          \
        int idx_ = q_ * 128 + tid;                                            \
        int r_ = idx_ >> 3, c_ = idx_ & 7;                                    \
        cp16(sb_ + r_ * 144 + c_ * 16,          g_kh + kbase_ + r_ * HS + c_ * 8);  \
        cp16(sb_ + 9216 + r_ * 144 + c_ * 16,   g_kl + kbase_ + r_ * HS + c_ * 8);  \
        cp16(sb_ + 18432 + r_ * 144 + c_ * 16,  g_vth + vbase_ + (size_t)r_ * TT + c_ * 8); \
    }                                                                         \
    asm volatile("cp.async.commit_group;");                                   \
} while (0)

__global__ void __launch_bounds__(128) attn_mma_kernel(float* __restrict__ out)
{
    extern __shared__ __align__(16) char smd[];
    __shared__ int sOld;
    const uint32_t smb = smem_u32(smd);
    const int pairI = blockIdx.x >> 1;
    const int p = blockIdx.x & 1;
    const int b = blockIdx.y;
    const int tid  = threadIdx.x;
    const int lane = tid & 31;
    const int w    = tid >> 5;
    const int lg   = lane >> 2;
    const int lt   = lane & 3;
    const int wrow = w * 16;

    const int gg = lane >> 3, ii = lane & 7;
    const uint32_t lih =
        (uint32_t)((((gg >> 1) * 8) + ii) * 144 + (gg & 1) * 16);

    for (int tt = 0; tt < 2; tt++) {
        const int qt = tt ? (31 - pairI) : pairI;
        const int q0 = qt * 64;

        // Q fragments straight from global bf16 (pre-scaled, pre-split)
        uint32_t qh[4][4], ql[4][4];
        {
            const size_t qb = ((size_t)b * TT + q0) * HS;
            #pragma unroll
            for (int kk = 0; kk < 4; kk++) {
                int h0 = kk * 16 + 2 * lt;
                qh[kk][0] = *(const uint32_t*)&g_qh[qb + (wrow + lg) * HS + h0];
                qh[kk][1] = *(const uint32_t*)&g_qh[qb + (wrow + lg + 8) * HS + h0];
                qh[kk][2] = *(const uint32_t*)&g_qh[qb + (wrow + lg) * HS + h0 + 8];
                qh[kk][3] = *(const uint32_t*)&g_qh[qb + (wrow + lg + 8) * HS + h0 + 8];
                ql[kk][0] = *(const uint32_t*)&g_ql[qb + (wrow + lg) * HS + h0];
                ql[kk][1] = *(const uint32_t*)&g_ql[qb + (wrow + lg + 8) * HS + h0];
                ql[kk][2] = *(const uint32_t*)&g_ql[qb + (wrow + lg) * HS + h0 + 8];
                ql[kk][3] = *(const uint32_t*)&g_ql[qb + (wrow + lg + 8) * HS + h0 + 8];
            }
        }

        float O[8][4];
        #pragma unroll
        for (int j = 0; j < 8; j++)
            #pragma unroll
            for (int e = 0; e < 4; e++) O[j][e] = 0.0f;
        float m0 = -1e30f, m1 = -1e30f, l0 = 0.0f, l1 = 0.0f;

        const int nkt = (qt >= p) ? (((qt - p) >> 1) + 1) : 0;

        __syncthreads();                 // stage buffers free before reuse
        if (nkt > 0) LOADSTAGE(0, p);

        for (int i = 0; i < nkt; i++) {
            const int kt = p + 2 * i;
            const int st = i & 1;
            if (i) __syncthreads();      // compute i-1 done before buf reuse
            if (i + 1 < nkt) {
                LOADSTAGE(st ^ 1, kt + 2);
                asm volatile("cp.async.wait_group 1;");
            } else {
                asm volatile("cp.async.wait_group 0;");
            }
            __syncthreads();

            const uint32_t smKh = smb + st * STG;
            const uint32_t smKl = smKh + 9216;
            const uint32_t smVh = smKh + 18432;

            // ---- S = Q K^T (bf16 3-term), B-frags via ldmatrix.x4
            float s[8][4];
            #pragma unroll
            for (int j = 0; j < 8; j++)
                #pragma unroll
                for (int e = 0; e < 4; e++) s[j][e] = 0.0f;

            #pragma unroll
            for (int kk = 0; kk < 4; kk++) {
                #pragma unroll
                for (int jp = 0; jp < 4; jp++) {
                    uint32_t bh[4], bl[4];
                    ldmx4(bh, smKh + lih + jp * 2304 + kk * 32);
                    ldmx4(bl, smKl + lih + jp * 2304 + kk * 32);
                    mma16816(s[2 * jp],     qh[kk], &bh[0]);
                    mma16816(s[2 * jp],     qh[kk], &bl[0]);
                    mma16816(s[2 * jp],     ql[kk], &bh[0]);
                    mma16816(s[2 * jp + 1], qh[kk], &bh[2]);
                    mma16816(s[2 * jp + 1], qh[kk], &bl[2]);
                    mma16816(s[2 * jp + 1], ql[kk], &bh[2]);
                }
            }

            // ---- causal mask (diagonal tile only)
            if (kt == qt) {
                #pragma unroll
                for (int j = 0; j < 8; j++) {
                    int lc = j * 8 + 2 * lt;
                    int r0 = wrow + lg, r1 = r0 + 8;
                    if (lc > r0)     s[j][0] = -1e30f;
                    if (lc + 1 > r0) s[j][1] = -1e30f;
                    if (lc > r1)     s[j][2] = -1e30f;
                    if (lc + 1 > r1) s[j][3] = -1e30f;
                }
            }

            // ---- online softmax
            {
                float mx0 = -1e30f, mx1 = -1e30f;
                #pragma unroll
                for (int j = 0; j < 8; j++) {
                    mx0 = fmaxf(mx0, fmaxf(s[j][0], s[j][1]));
                    mx1 = fmaxf(mx1, fmaxf(s[j][2], s[j][3]));
                }
                #pragma unroll
                for (int o = 1; o <= 2; o <<= 1) {
                    mx0 = fmaxf(mx0, __shfl_xor_sync(0xffffffffu, mx0, o));
                    mx1 = fmaxf(mx1, __shfl_xor_sync(0xffffffffu, mx1, o));
                }
                float mn0 = fmaxf(m0, mx0), mn1 = fmaxf(m1, mx1);
                float al0 = __expf(m0 - mn0), al1 = __expf(m1 - mn1);
                float sum0 = 0.0f, sum1 = 0.0f;
                #pragma unroll
                for (int j = 0; j < 8; j++) {
                    s[j][0] = __expf(s[j][0] - mn0);
                    s[j][1] = __expf(s[j][1] - mn0);
                    s[j][2] = __expf(s[j][2] - mn1);
                    s[j][3] = __expf(s[j][3] - mn1);
                    sum0 += s[j][0] + s[j][1];
                    sum1 += s[j][2] + s[j][3];
                }
                #pragma unroll
                for (int o = 1; o <= 2; o <<= 1) {
                    sum0 += __shfl_xor_sync(0xffffffffu, sum0, o);
                    sum1 += __shfl_xor_sync(0xffffffffu, sum1, o);
                }
                l0 = l0 * al0 + sum0;
                l1 = l1 * al1 + sum1;
                m0 = mn0; m1 = mn1;
                #pragma unroll
                for (int j = 0; j < 8; j++) {
                    O[j][0] *= al0; O[j][1] *= al0;
                    O[j][2] *= al1; O[j][3] *= al1;
                }
            }

            // ---- pack P -> fp16
            uint32_t pp[8][2];
            #pragma unroll
            for (int j = 0; j < 8; j++) {
                __half2 a01 = __floats2half2_rn(s[j][0], s[j][1]);
                __half2 a23 = __floats2half2_rn(s[j][2], s[j][3]);
                pp[j][0] = *(uint32_t*)&a01;
                pp[j][1] = *(uint32_t*)&a23;
            }

            // ---- O += P @ V (fp16 single-term), V-frags via ldmatrix.x4
            #pragma unroll
            for (int jhp = 0; jhp < 4; jhp++) {
                #pragma unroll
                for (int kk = 0; kk < 4; kk++) {
                    uint32_t vh[4];
                    ldmx4(vh, smVh + lih + jhp * 2304 + kk * 32);
                    uint32_t aP[4] = {pp[2 * kk][0], pp[2 * kk][1],
                                      pp[2 * kk + 1][0], pp[2 * kk + 1][1]};
                    mma16816h(O[2 * jhp],     aP, &vh[0]);
                    mma16816h(O[2 * jhp + 1], aP, &vh[2]);
                }
            }
        }

        // ---- write partial (unnormalized O, m, l)
        const size_t r0 = (size_t)b * TT + q0 + wrow + lg;
        {
            float* po = g_pO + (size_t)p * PSTRIDE;
            #pragma unroll
            for (int jh = 0; jh < 8; jh++) {
                int hcol = jh * 8 + 2 * lt;
                *(float2*)&po[r0 * HS + hcol] = make_float2(O[jh][0], O[jh][1]);
                *(float2*)&po[(r0 + 8) * HS + hcol] = make_float2(O[jh][2], O[jh][3]);
            }
            if (lt == 0) {
                g_pm[p * ROWS + r0] = m0;
                g_pl[p * ROWS + r0] = l0;
                g_pm[p * ROWS + r0 + 8] = m1;
                g_pl[p * ROWS + r0 + 8] = l1;
            }
        }

        // ---- arrival flag; second CTA merges (threadfence-reduction pattern)
        __threadfence();
        __syncthreads();
        if (tid == 0) sOld = atomicAdd(&g_flag[b * 32 + qt], 1);
        __syncthreads();

        if (sOld & 1) {
            const int po = p ^ 1;
            const float* pOo = g_pO + (size_t)po * PSTRIDE;
            float mo0 = g_pm[po * ROWS + r0];
            float lo0 = g_pl[po * ROWS + r0];
            float mo1 = g_pm[po * ROWS + r0 + 8];
            float lo1 = g_pl[po * ROWS + r0 + 8];
            float M0 = fmaxf(m0, mo0), M1 = fmaxf(m1, mo1);
            float wm0 = __expf(m0 - M0), wo0 = __expf(mo0 - M0);
            float wm1 = __expf(m1 - M1), wo1 = __expf(mo1 - M1);
            float inv0 = 1.0f / (wm0 * l0 + wo0 * lo0);
            float inv1 = 1.0f / (wm1 * l1 + wo1 * lo1);
            #pragma unroll
            for (int jh = 0; jh < 8; jh++) {
                int hcol = jh * 8 + 2 * lt;
                float2 a = *(const float2*)&pOo[r0 * HS + hcol];
                float2 c = *(const float2*)&pOo[(r0 + 8) * HS + hcol];
                float2 o0, o1;
                o0.x = (wm0 * O[jh][0] + wo0 * a.x) * inv0;
                o0.y = (wm0 * O[jh][1] + wo0 * a.y) * inv0;
                o1.x = (wm1 * O[jh][2] + wo1 * c.x) * inv1;
                o1.y = (wm1 * O[jh][3] + wo1 * c.y) * inv1;
                *(float2*)&out[r0 * HS + hcol] = o0;
                *(float2*)&out[(r0 + 8) * HS + hcol] = o1;
            }
        }
    }
}

// ---------------------------------------------------------------------------
extern "C" void kernel_launch(void* const* d_in, const int* in_sizes, int n_in,
                              void* d_out, int out_size)
{
    const float* X  = (const float*)d_in[0];
    const float* Wq = (const float*)d_in[1];
    const float* bq = (const float*)d_in[2];
    const float* Wk = (const float*)d_in[3];
    const float* bk = (const float*)d_in[4];
    const float* Wv = (const float*)d_in[5];
    const float* bv = (const float*)d_in[6];
    float* out = (float*)d_out;

    static int attr_set = 0;
    if (!attr_set) {
        cudaFuncSetAttribute(qkv_mma_kernel,
                             cudaFuncAttributeMaxDynamicSharedMemorySize,
                             SMEM_QKV);
        cudaFuncSetAttribute(attn_mma_kernel,
                             cudaFuncAttributeMaxDynamicSharedMemorySize,
                             2 * STG);
        attr_set = 1;
    }

    w_convert_kernel<<<48, 256>>>(Wq, Wk, Wv);
    qkv_mma_kernel<<<128, 256, SMEM_QKV>>>(X, bq, bk, bv);

    dim3 g2(32, BB);                       // pairs x parts, batches
    attn_mma_kernel<<<g2, 128, 2 * STG>>>(out);
}

// round 12
// speedup vs baseline: 1.0409x; 1.0409x over previous
#include <cuda_runtime.h>
#include <cuda_bf16.h>
#include <cuda_fp16.h>
#include <cstdint>

#define BB 8
#define TT 2048
#define EE 1024
#define HS 64
#define NTOT 192   // q(64) | k(64) | v(64)
#define ROWS (BB * TT)
#define PSTRIDE (BB * TT * HS)

// Preconverted operands (written by qkv epilogue)
__device__ __nv_bfloat16 g_qh[ROWS * HS];   // Q hi, pre-scaled 0.125, [B*T][64]
__device__ __nv_bfloat16 g_ql[ROWS * HS];
__device__ __nv_bfloat16 g_kh[ROWS * HS];   // K hi [B*T][64]
__device__ __nv_bfloat16 g_kl[ROWS * HS];
__device__ __half        g_vth[BB * HS * TT];  // V transposed [B][64h][2048t], fp16
// Weights fp16 hi/lo of (32*W)
__device__ __half g_Wh[NTOT * EE];
__device__ __half g_Wl[NTOT * EE];
// Attention partials (2 key-split parts)
__device__ float g_pO[2 * PSTRIDE];
__device__ float g_pm[2 * ROWS];
__device__ float g_pl[2 * ROWS];

// ---------------------------------------------------------------------------
// Helpers
// ---------------------------------------------------------------------------
__device__ __forceinline__ uint32_t smem_u32(const void* p) {
    uint32_t a;
    asm("{ .reg .u64 t; cvta.to.shared.u64 t, %1; cvt.u32.u64 %0, t; }"
        : "=r"(a) : "l"(p));
    return a;
}

__device__ __forceinline__ void cp16(uint32_t dst, const void* src) {
    asm volatile("cp.async.cg.shared.global [%0], [%1], 16;"
                 :: "r"(dst), "l"(src));
}

// bf16 mma, fp32 accum
__device__ __forceinline__ void mma16816(float* c, const uint32_t* a,
                                         const uint32_t* b) {
    asm volatile(
        "mma.sync.aligned.m16n8k16.row.col.f32.bf16.bf16.f32 "
        "{%0,%1,%2,%3}, {%4,%5,%6,%7}, {%8,%9}, {%0,%1,%2,%3};"
        : "+f"(c[0]), "+f"(c[1]), "+f"(c[2]), "+f"(c[3])
        : "r"(a[0]), "r"(a[1]), "r"(a[2]), "r"(a[3]), "r"(b[0]), "r"(b[1]));
}

// fp16 mma, fp32 accum
__device__ __forceinline__ void mma16816h(float* c, const uint32_t* a,
                                          const uint32_t* b) {
    asm volatile(
        "mma.sync.aligned.m16n8k16.row.col.f32.f16.f16.f32 "
        "{%0,%1,%2,%3}, {%4,%5,%6,%7}, {%8,%9}, {%0,%1,%2,%3};"
        : "+f"(c[0]), "+f"(c[1]), "+f"(c[2]), "+f"(c[3])
        : "r"(a[0]), "r"(a[1]), "r"(a[2]), "r"(a[3]), "r"(b[0]), "r"(b[1]));
}

// ldmatrix x4 (non-trans, b16)
__device__ __forceinline__ void ldmx4(uint32_t* r, uint32_t addr) {
    asm volatile(
        "ldmatrix.sync.aligned.m8n8.x4.shared.b16 {%0,%1,%2,%3}, [%4];"
        : "=r"(r[0]), "=r"(r[1]), "=r"(r[2]), "=r"(r[3]) : "r"(addr));
}

// ---------------------------------------------------------------------------
// Kernel 0: convert concat(Wq,Wk,Wv)*32 fp32 -> fp16 hi/lo, [192][1024]
// (R7 version: 192 blocks, one float4/thread)
// ---------------------------------------------------------------------------
__global__ __launch_bounds__(256) void w_convert_kernel(
    const float* __restrict__ Wq, const float* __restrict__ Wk,
    const float* __restrict__ Wv)
{
    int idx = blockIdx.x * 256 + threadIdx.x;
    int e4 = idx * 4;
    int n = e4 >> 10;
    int c = e4 & 1023;
    const float* src = (n < 64) ? &Wq[n * 1024 + c]
                     : (n < 128) ? &Wk[(n - 64) * 1024 + c]
                     : &Wv[(n - 128) * 1024 + c];
    float4 v = *(const float4*)src;
    float vs[4] = {v.x * 32.0f, v.y * 32.0f, v.z * 32.0f, v.w * 32.0f};
    __half h[4], l[4];
    #pragma unroll
    for (int e = 0; e < 4; e++) {
        h[e] = __float2half_rn(vs[e]);
        l[e] = __float2half_rn(vs[e] - __half2float(h[e]));
    }
    *(uint2*)&g_Wh[e4] = *(uint2*)h;
    *(uint2*)&g_Wl[e4] = *(uint2*)l;
}

// ---------------------------------------------------------------------------
// Kernel 1: QKV projection, fp16 2-term mma (exact R7).
// ---------------------------------------------------------------------------
#define ASTRIDE 80
#define BOFF  10240
#define STAGE 34816
#define SMEM_QKV (2 * STAGE)

__global__ void __launch_bounds__(256) qkv_mma_kernel(
    const float* __restrict__ X,
    const float* __restrict__ bq, const float* __restrict__ bk,
    const float* __restrict__ bv)
{
    extern __shared__ __align__(128) char sm[];
    const uint32_t smb = smem_u32(sm);
    const int tid = threadIdx.x;
    const int lid = tid & 31;
    const int wid = tid >> 5;
    const int wm  = wid >> 2;
    const int wn  = wid & 3;
    const int lg  = lid >> 2;
    const int lt  = lid & 3;
    const int m0  = blockIdx.x * 128;
    const int arow = tid >> 1;
    const int akh  = tid & 1;

    float acc[4][6][4];
    #pragma unroll
    for (int t = 0; t < 4; t++)
        #pragma unroll
        for (int u = 0; u < 6; u++)
            #pragma unroll
            for (int r = 0; r < 4; r++) acc[t][u][r] = 0.0f;

    float4 xr[4];

    {
        const float* xp = &X[(size_t)(m0 + arow) * EE + akh * 16];
        #pragma unroll
        for (int p = 0; p < 4; p++) xr[p] = *(const float4*)&xp[p * 4];
        #pragma unroll
        for (int j = 0; j < 6; j++) {
            int idx = j * 256 + tid;
            int n = idx >> 3, u = idx & 7;
            int kg = u & 3, wh = u >> 2;
            const __half* s = (wh ? g_Wl : g_Wh) + n * EE + kg * 8;
            cp16(smb + BOFF + n * 128 + ((u ^ (n & 7)) * 16), s);
        }
        asm volatile("cp.async.commit_group;");
        {
            __half2 hh[8];
            #pragma unroll
            for (int p = 0; p < 4; p++) {
                hh[2 * p]     = __floats2half2_rn(xr[p].x, xr[p].y);
                hh[2 * p + 1] = __floats2half2_rn(xr[p].z, xr[p].w);
            }
            *(uint4*)(sm + arow * ASTRIDE + akh * 32)      = *(uint4*)&hh[0];
            *(uint4*)(sm + arow * ASTRIDE + akh * 32 + 16) = *(uint4*)&hh[4];
        }
        asm volatile("cp.async.wait_group 0;");
        __syncthreads();
    }

    for (int c = 0; c < 32; c++) {
        const int cb = c & 1;
        const int nb = (c + 1) & 1;
        if (c < 31) {
            const int k0 = (c + 1) * 32;
            const float* xp = &X[(size_t)(m0 + arow) * EE + k0 + akh * 16];
            #pragma unroll
            for (int p = 0; p < 4; p++) xr[p] = *(const float4*)&xp[p * 4];
            #pragma unroll
            for (int j = 0; j < 6; j++) {
                int idx = j * 256 + tid;
                int n = idx >> 3, u = idx & 7;
                int kg = u & 3, wh = u >> 2;
                const __half* s = (wh ? g_Wl : g_Wh) + n * EE + k0 + kg * 8;
                cp16(smb + nb * STAGE + BOFF + n * 128 + ((u ^ (n & 7)) * 16), s);
            }
            asm volatile("cp.async.commit_group;");
        }

        const char* ab = sm + cb * STAGE;
        const char* bb = ab + BOFF;
        #pragma unroll
        for (int h = 0; h < 2; h++) {
            uint32_t af[4][4], bfh[6][2], bfl[6][2];
            #pragma unroll
            for (int t = 0; t < 4; t++) {
                int r  = wm * 64 + t * 16 + lg;
                int r8 = r + 8;
                af[t][0] = *(const uint32_t*)(ab + r  * ASTRIDE + (2 * h) * 16 + lt * 4);
                af[t][1] = *(const uint32_t*)(ab + r8 * ASTRIDE + (2 * h) * 16 + lt * 4);
                af[t][2] = *(const uint32_t*)(ab + r  * ASTRIDE + (2 * h + 1) * 16 + lt * 4);
                af[t][3] = *(const uint32_t*)(ab + r8 * ASTRIDE + (2 * h + 1) * 16 + lt * 4);
            }
            #pragma unroll
            for (int u = 0; u < 6; u++) {
                int n = wn * 48 + u * 8 + lg;
                int kg0 = 2 * h, kg1 = 2 * h + 1;
                bfh[u][0] = *(const uint32_t*)(bb + n * 128 + ((kg0 ^ (n & 7)) * 16) + lt * 4);
                bfh[u][1] = *(const uint32_t*)(bb + n * 128 + ((kg1 ^ (n & 7)) * 16) + lt * 4);
                bfl[u][0] = *(const uint32_t*)(bb + n * 128 + (((kg0 | 4) ^ (n & 7)) * 16) + lt * 4);
                bfl[u][1] = *(const uint32_t*)(bb + n * 128 + (((kg1 | 4) ^ (n & 7)) * 16) + lt * 4);
            }
            #pragma unroll
            for (int t = 0; t < 4; t++)
                #pragma unroll
                for (int u = 0; u < 6; u++)
                    mma16816h(acc[t][u], af[t], bfh[u]);
            #pragma unroll
            for (int t = 0; t < 4; t++)
                #pragma unroll
                for (int u = 0; u < 6; u++)
                    mma16816h(acc[t][u], af[t], bfl[u]);
        }

        if (c < 31) {
            __half2 hh[8];
            #pragma unroll
            for (int p = 0; p < 4; p++) {
                hh[2 * p]     = __floats2half2_rn(xr[p].x, xr[p].y);
                hh[2 * p + 1] = __floats2half2_rn(xr[p].z, xr[p].w);
            }
            *(uint4*)(sm + nb * STAGE + arow * ASTRIDE + akh * 32)      = *(uint4*)&hh[0];
            *(uint4*)(sm + nb * STAGE + arow * ASTRIDE + akh * 32 + 16) = *(uint4*)&hh[4];
            asm volatile("cp.async.wait_group 0;");
        }
        __syncthreads();
    }

    // ---- epilogue: acc/32 + bias; Q/K -> bf16 hi/lo; V -> fp16 via smem T
    __half* VtSh = (__half*)sm;                  // [64h][128 rl]

    #pragma unroll
    for (int t = 0; t < 4; t++) {
        int rl = wm * 64 + t * 16 + lg;
        size_t rg = (size_t)(m0 + rl);
        #pragma unroll
        for (int u = 0; u < 6; u++) {
            int n = wn * 48 + u * 8 + lt * 2;
            const float* barr; int col; int kind;
            if (n < 64)       { col = n;       barr = bq; kind = 0; }
            else if (n < 128) { col = n - 64;  barr = bk; kind = 1; }
            else              { col = n - 128; barr = bv; kind = 2; }
            float b0 = __ldg(&barr[col]), b1 = __ldg(&barr[col + 1]);
            float v00 = acc[t][u][0] * 0.03125f + b0;
            float v01 = acc[t][u][1] * 0.03125f + b1;
            float v10 = acc[t][u][2] * 0.03125f + b0;
            float v11 = acc[t][u][3] * 0.03125f + b1;
            if (kind == 0) {
                v00 *= 0.125f; v01 *= 0.125f; v10 *= 0.125f; v11 *= 0.125f;
            }
            if (kind < 2) {
                __nv_bfloat16* dh = kind ? g_kh : g_qh;
                __nv_bfloat16* dl = kind ? g_kl : g_ql;
                __nv_bfloat162 h0p = __floats2bfloat162_rn(v00, v01);
                float2 f0 = __bfloat1622float2(h0p);
                __nv_bfloat162 l0p = __floats2bfloat162_rn(v00 - f0.x, v01 - f0.y);
                __nv_bfloat162 h1p = __floats2bfloat162_rn(v10, v11);
                float2 f1 = __bfloat1622float2(h1p);
                __nv_bfloat162 l1p = __floats2bfloat162_rn(v10 - f1.x, v11 - f1.y);
                *(uint32_t*)&dh[rg * HS + col]       = *(uint32_t*)&h0p;
                *(uint32_t*)&dl[rg * HS + col]       = *(uint32_t*)&l0p;
                *(uint32_t*)&dh[(rg + 8) * HS + col] = *(uint32_t*)&h1p;
                *(uint32_t*)&dl[(rg + 8) * HS + col] = *(uint32_t*)&l1p;
            } else {
                VtSh[col * 128 + rl]           = __float2half_rn(v00);
                VtSh[(col + 1) * 128 + rl]     = __float2half_rn(v01);
                VtSh[col * 128 + rl + 8]       = __float2half_rn(v10);
                VtSh[(col + 1) * 128 + rl + 8] = __float2half_rn(v11);
            }
        }
    }
    __syncthreads();
    {
        int bbb = m0 >> 11, t0 = m0 & 2047;
        #pragma unroll
        for (int q = 0; q < 4; q++) {
            int idx = q * 256 + tid;
            int h = idx >> 4, cc = idx & 15;
            __half* dst = g_vth + ((size_t)(bbb * HS + h)) * TT + t0 + cc * 8;
            *(uint4*)dst = *(const uint4*)(VtSh + h * 128 + cc * 8);
        }
    }
}

// ---------------------------------------------------------------------------
// Kernel 2: causal flash attention (R7 scheduling) with FA2-style skewed
// pipeline: S-mma for step i+1 is issued right after softmax(i), before
// PV(i), so the tensor pipe stays fed across softmax phases.
// ---------------------------------------------------------------------------
#define STG 27648

#define LOADSTAGE(st_, kt_) do {                                              \
    uint32_t sb_ = smb + (st_) * STG;                                         \
    size_t kbase_ = ((size_t)b * TT + (size_t)(kt_) * 64) * HS;               \
    size_t vbase_ = (size_t)b * (HS * TT) + (size_t)(kt_) * 64;               \
    _Pragma("unroll")                                                         \
    for (int q_ = 0; q_ < 4; q_++) {                                          \
        int idx_ = q_ * 128 + tid;                                            \
        int r_ = idx_ >> 3, c_ = idx_ & 7;                                    \
        cp16(sb_ + r_ * 144 + c_ * 16,          g_kh + kbase_ + r_ * HS + c_ * 8);  \
        cp16(sb_ + 9216 + r_ * 144 + c_ * 16,   g_kl + kbase_ + r_ * HS + c_ * 8);  \
        cp16(sb_ + 18432 + r_ * 144 + c_ * 16,  g_vth + vbase_ + (size_t)r_ * TT + c_ * 8); \
    }                                                                         \
    asm volatile("cp.async.commit_group;");                                   \
} while (0)

// Compute s[8][4] = Q K^T (bf16 3-term) from stage buffer stb_
#define SMMA(stb_) do {                                                       \
    const uint32_t smKh_ = smb + (stb_) * STG;                                \
    const uint32_t smKl_ = smKh_ + 9216;                                      \
    _Pragma("unroll")                                                         \
    for (int j_ = 0; j_ < 8; j_++)                                            \
        _Pragma("unroll")                                                     \
        for (int e_ = 0; e_ < 4; e_++) s[j_][e_] = 0.0f;                      \
    _Pragma("unroll")                                                         \
    for (int kk_ = 0; kk_ < 4; kk_++) {                                       \
        _Pragma("unroll")                                                     \
        for (int jp_ = 0; jp_ < 4; jp_++) {                                   \
            uint32_t bh_[4], bl_[4];                                          \
            ldmx4(bh_, smKh_ + lih + jp_ * 2304 + kk_ * 32);                  \
            ldmx4(bl_, smKl_ + lih + jp_ * 2304 + kk_ * 32);                  \
            mma16816(s[2 * jp_],     qh[kk_], &bh_[0]);                       \
            mma16816(s[2 * jp_],     qh[kk_], &bl_[0]);                       \
            mma16816(s[2 * jp_],     ql[kk_], &bh_[0]);                       \
            mma16816(s[2 * jp_ + 1], qh[kk_], &bh_[2]);                       \
            mma16816(s[2 * jp_ + 1], qh[kk_], &bl_[2]);                       \
            mma16816(s[2 * jp_ + 1], ql[kk_], &bh_[2]);                       \
        }                                                                     \
    }                                                                         \
} while (0)

__global__ void __launch_bounds__(128) attn_mma_kernel()
{
    extern __shared__ __align__(16) char smd[];
    const uint32_t smb = smem_u32(smd);
    const int pairI = blockIdx.x >> 1;
    const int p = blockIdx.x & 1;
    const int b = blockIdx.y;
    const int tid  = threadIdx.x;
    const int lane = tid & 31;
    const int w    = tid >> 5;
    const int lg   = lane >> 2;
    const int lt   = lane & 3;
    const int wrow = w * 16;

    const int gg = lane >> 3, ii = lane & 7;
    const uint32_t lih =
        (uint32_t)((((gg >> 1) * 8) + ii) * 144 + (gg & 1) * 16);

    for (int tt = 0; tt < 2; tt++) {
        const int qt = tt ? (31 - pairI) : pairI;
        const int q0 = qt * 64;

        // Q fragments straight from global bf16 (pre-scaled, pre-split)
        uint32_t qh[4][4], ql[4][4];
        {
            const size_t qb = ((size_t)b * TT + q0) * HS;
            #pragma unroll
            for (int kk = 0; kk < 4; kk++) {
                int h0 = kk * 16 + 2 * lt;
                qh[kk][0] = *(const uint32_t*)&g_qh[qb + (wrow + lg) * HS + h0];
                qh[kk][1] = *(const uint32_t*)&g_qh[qb + (wrow + lg + 8) * HS + h0];
                qh[kk][2] = *(const uint32_t*)&g_qh[qb + (wrow + lg) * HS + h0 + 8];
                qh[kk][3] = *(const uint32_t*)&g_qh[qb + (wrow + lg + 8) * HS + h0 + 8];
                ql[kk][0] = *(const uint32_t*)&g_ql[qb + (wrow + lg) * HS + h0];
                ql[kk][1] = *(const uint32_t*)&g_ql[qb + (wrow + lg + 8) * HS + h0];
                ql[kk][2] = *(const uint32_t*)&g_ql[qb + (wrow + lg) * HS + h0 + 8];
                ql[kk][3] = *(const uint32_t*)&g_ql[qb + (wrow + lg + 8) * HS + h0 + 8];
            }
        }

        float O[8][4];
        #pragma unroll
        for (int j = 0; j < 8; j++)
            #pragma unroll
            for (int e = 0; e < 4; e++) O[j][e] = 0.0f;
        float m0 = -1e30f, m1 = -1e30f, l0 = 0.0f, l1 = 0.0f;

        const int nkt = (qt >= p) ? (((qt - p) >> 1) + 1) : 0;

        float s[8][4];

        __syncthreads();                 // prev tile's reads of buffers done
        if (nkt > 0) {
            LOADSTAGE(0, p);
            asm volatile("cp.async.wait_group 0;");
            __syncthreads();             // buf0 published
            SMMA(0);                     // S(0)
            if (nkt > 1) LOADSTAGE(1, p + 2);
        }

        for (int i = 0; i < nkt; i++) {
            const int kt = p + 2 * i;
            const int st = i & 1;

            // ---- causal mask (diagonal tile only)
            if (kt == qt) {
                #pragma unroll
                for (int j = 0; j < 8; j++) {
                    int lc = j * 8 + 2 * lt;
                    int r0 = wrow + lg, r1 = r0 + 8;
                    if (lc > r0)     s[j][0] = -1e30f;
                    if (lc + 1 > r0) s[j][1] = -1e30f;
                    if (lc > r1)     s[j][2] = -1e30f;
                    if (lc + 1 > r1) s[j][3] = -1e30f;
                }
            }

            // ---- online softmax on s -> pp; s becomes dead after this
            uint32_t pp[8][2];
            {
                float mx0 = -1e30f, mx1 = -1e30f;
                #pragma unroll
                for (int j = 0; j < 8; j++) {
                    mx0 = fmaxf(mx0, fmaxf(s[j][0], s[j][1]));
                    mx1 = fmaxf(mx1, fmaxf(s[j][2], s[j][3]));
                }
                #pragma unroll
                for (int o = 1; o <= 2; o <<= 1) {
                    mx0 = fmaxf(mx0, __shfl_xor_sync(0xffffffffu, mx0, o));
                    mx1 = fmaxf(mx1, __shfl_xor_sync(0xffffffffu, mx1, o));
                }
                float mn0 = fmaxf(m0, mx0), mn1 = fmaxf(m1, mx1);
                float al0 = __expf(m0 - mn0), al1 = __expf(m1 - mn1);
                float sum0 = 0.0f, sum1 = 0.0f;
                #pragma unroll
                for (int j = 0; j < 8; j++) {
                    float e0 = __expf(s[j][0] - mn0);
                    float e1 = __expf(s[j][1] - mn0);
                    float e2 = __expf(s[j][2] - mn1);
                    float e3 = __expf(s[j][3] - mn1);
                    sum0 += e0 + e1;
                    sum1 += e2 + e3;
                    __half2 a01 = __floats2half2_rn(e0, e1);
                    __half2 a23 = __floats2half2_rn(e2, e3);
                    pp[j][0] = *(uint32_t*)&a01;
                    pp[j][1] = *(uint32_t*)&a23;
                }
                #pragma unroll
                for (int o = 1; o <= 2; o <<= 1) {
                    sum0 += __shfl_xor_sync(0xffffffffu, sum0, o);
                    sum1 += __shfl_xor_sync(0xffffffffu, sum1, o);
                }
                l0 = l0 * al0 + sum0;
                l1 = l1 * al1 + sum1;
                m0 = mn0; m1 = mn1;
                #pragma unroll
                for (int j = 0; j < 8; j++) {
                    O[j][0] *= al0; O[j][1] *= al0;
                    O[j][2] *= al1; O[j][3] *= al1;
                }
            }

            // ---- issue S(i+1) now (buffer st^1 just published) so its
            //      tensor work overlaps PV(i) and the next softmax's wait
            if (i + 1 < nkt) {
                asm volatile("cp.async.wait_group 0;");
                __syncthreads();         // publish buf(i+1)
                SMMA(st ^ 1);
            }

            // ---- O += P(i) @ V(i) (fp16 single-term) from buf st
            {
                const uint32_t smVh = smb + st * STG + 18432;
                #pragma unroll
                for (int jhp = 0; jhp < 4; jhp++) {
                    #pragma unroll
                    for (int kk = 0; kk < 4; kk++) {
                        uint32_t vh[4];
                        ldmx4(vh, smVh + lih + jhp * 2304 + kk * 32);
                        uint32_t aP[4] = {pp[2 * kk][0], pp[2 * kk][1],
                                          pp[2 * kk + 1][0], pp[2 * kk + 1][1]};
                        mma16816h(O[2 * jhp],     aP, &vh[0]);
                        mma16816h(O[2 * jhp + 1], aP, &vh[2]);
                    }
                }
            }

            // ---- free buf st for load(i+2)
            if (i + 2 < nkt) {
                __syncthreads();         // all warps done reading buf st
                LOADSTAGE(st, kt + 4);
            }
        }

        // ---- write partial (unnormalized O, m, l)
        {
            const size_t r0 = (size_t)b * TT + q0 + wrow + lg;
            float* po = g_pO + (size_t)p * PSTRIDE;
            #pragma unroll
            for (int jh = 0; jh < 8; jh++) {
                int hcol = jh * 8 + 2 * lt;
                *(float2*)&po[r0 * HS + hcol] = make_float2(O[jh][0], O[jh][1]);
                *(float2*)&po[(r0 + 8) * HS + hcol] = make_float2(O[jh][2], O[jh][3]);
            }
            if (lt == 0) {
                g_pm[p * ROWS + r0] = m0;
                g_pl[p * ROWS + r0] = l0;
                g_pm[p * ROWS + r0 + 8] = m1;
                g_pl[p * ROWS + r0 + 8] = l1;
            }
        }
    }
}

// ---------------------------------------------------------------------------
// Kernel 3: merge the two key-split partials (exact R7).
// ---------------------------------------------------------------------------
__global__ __launch_bounds__(256) void combine_kernel(float* __restrict__ out)
{
    int idx = blockIdx.x * 256 + threadIdx.x;    // 262144 total
    int row = idx >> 4;
    int h4 = (idx & 15) * 4;
    float m0 = g_pm[row], m1 = g_pm[ROWS + row];
    float l0 = g_pl[row], l1 = g_pl[ROWS + row];
    float M = fmaxf(m0, m1);
    float w0 = __expf(m0 - M), w1 = __expf(m1 - M);
    float inv = 1.0f / (w0 * l0 + w1 * l1);
    float4 a = *(const float4*)&g_pO[(size_t)row * HS + h4];
    float4 c = *(const float4*)&g_pO[PSTRIDE + (size_t)row * HS + h4];
    float4 o;
    o.x = (w0 * a.x + w1 * c.x) * inv;
    o.y = (w0 * a.y + w1 * c.y) * inv;
    o.z = (w0 * a.z + w1 * c.z) * inv;
    o.w = (w0 * a.w + w1 * c.w) * inv;
    *(float4*)&out[(size_t)row * HS + h4] = o;
}

// ---------------------------------------------------------------------------
extern "C" void kernel_launch(void* const* d_in, const int* in_sizes, int n_in,
                              void* d_out, int out_size)
{
    const float* X  = (const float*)d_in[0];
    const float* Wq = (const float*)d_in[1];
    const float* bq = (const float*)d_in[2];
    const float* Wk = (const float*)d_in[3];
    const float* bk = (const float*)d_in[4];
    const float* Wv = (const float*)d_in[5];
    const float* bv = (const float*)d_in[6];
    float* out = (float*)d_out;

    static int attr_set = 0;
    if (!attr_set) {
        cudaFuncSetAttribute(qkv_mma_kernel,
                             cudaFuncAttributeMaxDynamicSharedMemorySize,
                             SMEM_QKV);
        cudaFuncSetAttribute(attn_mma_kernel,
                             cudaFuncAttributeMaxDynamicSharedMemorySize,
                             2 * STG);
        attr_set = 1;
    }

    w_convert_kernel<<<192, 256>>>(Wq, Wk, Wv);
    qkv_mma_kernel<<<128, 256, SMEM_QKV>>>(X, bq, bk, bv);

    dim3 g2(32, BB);                       // pairs x parts, batches
    attn_mma_kernel<<<g2, 128, 2 * STG>>>();

    combine_kernel<<<ROWS * HS / 4 / 256, 256>>>(out);
}